// round 1
// baseline (speedup 1.0000x reference)
#include <cuda_runtime.h>

#define S_LEN 8192
#define DIM   1024
#define NH    16
#define HD    64
#define WIN   512

// Scratch (device globals: allocation-guard safe). 4 x 32MB.
__device__ float g_Q[S_LEN * DIM];
__device__ float g_K[S_LEN * DIM];
__device__ float g_V[S_LEN * DIM];
__device__ float g_O[S_LEN * DIM];

// ---------------------------------------------------------------------------
// SGEMM NT: C[M,N] = A[M,K] * B[N,K]^T   (torch Linear convention)
// 128x128 tile, BK=8, 256 threads, 8x8 accumulators per thread.
// ---------------------------------------------------------------------------
__global__ __launch_bounds__(256) void sgemm_nt(const float* __restrict__ A,
                                                const float* __restrict__ B,
                                                float* __restrict__ C,
                                                int M, int N, int K)
{
    __shared__ float As[8][128];
    __shared__ float Bs[8][128];

    const int tid = threadIdx.x;
    const int tx  = tid & 15;
    const int ty  = tid >> 4;
    const int m0  = blockIdx.y * 128;
    const int n0  = blockIdx.x * 128;

    const int lrow = tid >> 1;        // 0..127
    const int lcol = (tid & 1) * 4;   // 0 or 4
    const float* Ap = A + (size_t)(m0 + lrow) * K + lcol;
    const float* Bp = B + (size_t)(n0 + lrow) * K + lcol;

    float acc[8][8];
#pragma unroll
    for (int i = 0; i < 8; i++)
#pragma unroll
        for (int j = 0; j < 8; j++) acc[i][j] = 0.f;

    for (int k0 = 0; k0 < K; k0 += 8) {
        float4 a = *(const float4*)(Ap + k0);
        float4 b = *(const float4*)(Bp + k0);
        As[lcol + 0][lrow] = a.x; As[lcol + 1][lrow] = a.y;
        As[lcol + 2][lrow] = a.z; As[lcol + 3][lrow] = a.w;
        Bs[lcol + 0][lrow] = b.x; Bs[lcol + 1][lrow] = b.y;
        Bs[lcol + 2][lrow] = b.z; Bs[lcol + 3][lrow] = b.w;
        __syncthreads();

#pragma unroll
        for (int kk = 0; kk < 8; kk++) {
            float ar[8], br[8];
            *(float4*)&ar[0] = *(const float4*)&As[kk][ty * 4];
            *(float4*)&ar[4] = *(const float4*)&As[kk][64 + ty * 4];
            *(float4*)&br[0] = *(const float4*)&Bs[kk][tx * 4];
            *(float4*)&br[4] = *(const float4*)&Bs[kk][64 + tx * 4];
#pragma unroll
            for (int i = 0; i < 8; i++)
#pragma unroll
                for (int j = 0; j < 8; j++)
                    acc[i][j] = fmaf(ar[i], br[j], acc[i][j]);
        }
        __syncthreads();
    }

#pragma unroll
    for (int ig = 0; ig < 2; ig++)
#pragma unroll
        for (int i = 0; i < 4; i++) {
            int row = m0 + ig * 64 + ty * 4 + i;
            float* Cp = C + (size_t)row * N + n0;
            float4 v0 = make_float4(acc[ig*4+i][0], acc[ig*4+i][1],
                                    acc[ig*4+i][2], acc[ig*4+i][3]);
            float4 v1 = make_float4(acc[ig*4+i][4], acc[ig*4+i][5],
                                    acc[ig*4+i][6], acc[ig*4+i][7]);
            *(float4*)(Cp + tx * 4)      = v0;
            *(float4*)(Cp + 64 + tx * 4) = v1;
        }
}

// ---------------------------------------------------------------------------
// RoPE (interleaved pairs) applied in-place to g_Q and g_K.
// pair p in row: head h = p/32, freq index i = p%32; columns (2p, 2p+1).
// ---------------------------------------------------------------------------
__global__ __launch_bounds__(256) void rope_kernel()
{
    int idx = blockIdx.x * blockDim.x + threadIdx.x;   // S * 512 threads
    if (idx >= S_LEN * (DIM / 2)) return;
    int s = idx >> 9;        // /512
    int p = idx & 511;
    int i = p & 31;

    // inv_freq = 10000^(-2i/64); exponent computed in double, exp2f ~1 ULP
    float e   = (float)(-(double)(2 * i) * 13.287712379549449 / 64.0); // log2(10000)
    float inv = exp2f(e);
    float ang = (float)s * inv;
    float sn, cs;
    sincosf(ang, &sn, &cs);

    size_t off = (size_t)s * DIM + 2 * p;
    float q1 = g_Q[off], q2 = g_Q[off + 1];
    g_Q[off]     = q1 * cs - q2 * sn;
    g_Q[off + 1] = q1 * sn + q2 * cs;
    float k1 = g_K[off], k2 = g_K[off + 1];
    g_K[off]     = k1 * cs - k2 * sn;
    g_K[off + 1] = k1 * sn + k2 * cs;
}

// ---------------------------------------------------------------------------
// Sliding-window attention (flash-style, online softmax, fp32).
// grid: (S/64 query tiles, NH heads); 256 threads = 16x16.
// Each thread owns a 4q x 4k score block and a 4q x 4d output block.
// Smem: Qs [d][q], KP (K as [d][k], reused as P [q][k]), Vs [k][d] = 48KB.
// ---------------------------------------------------------------------------
__global__ __launch_bounds__(256) void swa_kernel()
{
    __shared__ float Qs[64][64];
    __shared__ float KP[64][64];
    __shared__ float Vs[64][64];

    const int h  = blockIdx.y;
    const int q0 = blockIdx.x << 6;
    const int tid = threadIdx.x;
    const int tx  = tid & 15;
    const int ty  = tid >> 4;

    // load Q tile transposed: Qs[d][q]
    {
        const int qr  = tid >> 2;
        const int seg = (tid & 3) << 4;
        const float* src = g_Q + (size_t)(q0 + qr) * DIM + h * HD + seg;
#pragma unroll
        for (int j = 0; j < 16; j += 4) {
            float4 v = *(const float4*)(src + j);
            Qs[seg + j + 0][qr] = v.x; Qs[seg + j + 1][qr] = v.y;
            Qs[seg + j + 2][qr] = v.z; Qs[seg + j + 3][qr] = v.w;
        }
    }

    float m[4], l[4], acc[4][4];
#pragma unroll
    for (int r = 0; r < 4; r++) {
        m[r] = -1e30f; l[r] = 0.f;
#pragma unroll
        for (int c = 0; c < 4; c++) acc[r][c] = 0.f;
    }

    const int kt_begin = (q0 >= WIN) ? ((q0 - (WIN - 1)) >> 6) : 0;
    const int kt_end   = q0 >> 6;                     // inclusive
    const float sc = 0.125f * 1.4426950408889634f;    // 1/sqrt(64) * log2(e)

    for (int kt = kt_begin; kt <= kt_end; kt++) {
        const int k0 = kt << 6;
        __syncthreads();   // prev-iter KP/Vs reads done; also covers Qs on iter 0

        // K tile transposed into KP[d][k]
        {
            const int kr  = tid >> 2;
            const int seg = (tid & 3) << 4;
            const float* srcK = g_K + (size_t)(k0 + kr) * DIM + h * HD + seg;
#pragma unroll
            for (int j = 0; j < 16; j += 4) {
                float4 v = *(const float4*)(srcK + j);
                KP[seg + j + 0][kr] = v.x; KP[seg + j + 1][kr] = v.y;
                KP[seg + j + 2][kr] = v.z; KP[seg + j + 3][kr] = v.w;
            }
            // V tile natural layout Vs[k][d]
#pragma unroll
            for (int t = 0; t < 4; t++) {
                int f   = tid + (t << 8);
                int kr2 = f >> 4;
                int dc  = (f & 15) << 2;
                *(float4*)&Vs[kr2][dc] =
                    *(const float4*)(g_V + (size_t)(k0 + kr2) * DIM + h * HD + dc);
            }
        }
        __syncthreads();

        // scores S = Q K^T (4x4 per thread)
        float s[4][4];
#pragma unroll
        for (int r = 0; r < 4; r++)
#pragma unroll
            for (int c = 0; c < 4; c++) s[r][c] = 0.f;
#pragma unroll
        for (int kk = 0; kk < 64; kk++) {
            float4 a = *(const float4*)&Qs[kk][ty << 2];
            float4 b = *(const float4*)&KP[kk][tx << 2];
            float av[4] = {a.x, a.y, a.z, a.w};
            float bv[4] = {b.x, b.y, b.z, b.w};
#pragma unroll
            for (int r = 0; r < 4; r++)
#pragma unroll
                for (int c = 0; c < 4; c++)
                    s[r][c] = fmaf(av[r], bv[c], s[r][c]);
        }

        // mask + scale into log2 domain
#pragma unroll
        for (int r = 0; r < 4; r++) {
            int qg = q0 + (ty << 2) + r;
#pragma unroll
            for (int c = 0; c < 4; c++) {
                int kg = k0 + (tx << 2) + c;
                bool ok = (kg <= qg) && (kg + WIN > qg);   // kg in [qg-511, qg]
                s[r][c] = ok ? s[r][c] * sc : -3.0e38f;
            }
        }

        // online softmax stats (rows span 16 tx lanes; xor-shuffle within group)
#pragma unroll
        for (int r = 0; r < 4; r++) {
            float mt = fmaxf(fmaxf(s[r][0], s[r][1]), fmaxf(s[r][2], s[r][3]));
#pragma unroll
            for (int o = 8; o > 0; o >>= 1)
                mt = fmaxf(mt, __shfl_xor_sync(0xffffffffu, mt, o));
            float mnew = fmaxf(m[r], mt);
            float corr = exp2f(m[r] - mnew);
            float sum  = 0.f;
#pragma unroll
            for (int c = 0; c < 4; c++) {
                float p = exp2f(s[r][c] - mnew);
                s[r][c] = p;
                sum += p;
            }
#pragma unroll
            for (int o = 8; o > 0; o >>= 1)
                sum += __shfl_xor_sync(0xffffffffu, sum, o);
            l[r] = l[r] * corr + sum;
            m[r] = mnew;
#pragma unroll
            for (int c = 0; c < 4; c++) acc[r][c] *= corr;
        }

        __syncthreads();   // all K reads done; reuse KP as P[q][k]
#pragma unroll
        for (int r = 0; r < 4; r++)
#pragma unroll
            for (int c = 0; c < 4; c++)
                KP[(ty << 2) + r][(tx << 2) + c] = s[r][c];
        __syncthreads();

        // O += P V (4x4 per thread, same q rows as softmax stats)
#pragma unroll
        for (int kk = 0; kk < 64; kk++) {
            float4 vv = *(const float4*)&Vs[kk][tx << 2];
            float vvv[4] = {vv.x, vv.y, vv.z, vv.w};
#pragma unroll
            for (int r = 0; r < 4; r++) {
                float p = KP[(ty << 2) + r][kk];
#pragma unroll
                for (int c = 0; c < 4; c++)
                    acc[r][c] = fmaf(p, vvv[c], acc[r][c]);
            }
        }
    }

    // epilogue: O /= l
#pragma unroll
    for (int r = 0; r < 4; r++) {
        float inv = 1.f / l[r];
        float4 o = make_float4(acc[r][0] * inv, acc[r][1] * inv,
                               acc[r][2] * inv, acc[r][3] * inv);
        *(float4*)(g_O + (size_t)(q0 + (ty << 2) + r) * DIM + h * HD + (tx << 2)) = o;
    }
}

// ---------------------------------------------------------------------------
extern "C" void kernel_launch(void* const* d_in, const int* in_sizes, int n_in,
                              void* d_out, int out_size)
{
    const float* x  = (const float*)d_in[0];
    const float* Wq = (const float*)d_in[1];
    const float* Wk = (const float*)d_in[2];
    const float* Wv = (const float*)d_in[3];
    const float* Wo = (const float*)d_in[4];
    float* out = (float*)d_out;
    (void)in_sizes; (void)n_in; (void)out_size;

    static float *pQ = nullptr, *pK = nullptr, *pV = nullptr, *pO = nullptr;
    if (!pQ) {
        cudaGetSymbolAddress((void**)&pQ, g_Q);
        cudaGetSymbolAddress((void**)&pK, g_K);
        cudaGetSymbolAddress((void**)&pV, g_V);
        cudaGetSymbolAddress((void**)&pO, g_O);
    }

    dim3 gp(DIM / 128, S_LEN / 128);
    sgemm_nt<<<gp, 256>>>(x, Wq, pQ, S_LEN, DIM, DIM);
    sgemm_nt<<<gp, 256>>>(x, Wk, pK, S_LEN, DIM, DIM);
    sgemm_nt<<<gp, 256>>>(x, Wv, pV, S_LEN, DIM, DIM);

    rope_kernel<<<(S_LEN * (DIM / 2)) / 256, 256>>>();

    swa_kernel<<<dim3(S_LEN / 64, NH), 256>>>();

    sgemm_nt<<<gp, 256>>>(pO, Wo, out, S_LEN, DIM, DIM);
}

// round 4
// speedup vs baseline: 1.9576x; 1.9576x over previous
#include <cuda_runtime.h>
#include <cuda_bf16.h>
#include <cstdint>

#define S_LEN 8192
#define DIM   1024
#define NH    16
#define HD    64
#define WIN   512

// Scratch (device globals: allocation-guard safe). 4 x 32MB.
__device__ float g_Q[S_LEN * DIM];
__device__ float g_K[S_LEN * DIM];
__device__ float g_V[S_LEN * DIM];
__device__ float g_O[S_LEN * DIM];

// ===========================================================================
// mma.sync helpers (sm_80+ path: no tcgen05 — harness PTX target is sm_100
// base, which gates off all arch-'a' features)
// ===========================================================================
__device__ __forceinline__ uint32_t smem_to_u32(const void* p) {
    uint32_t a;
    asm("{ .reg .u64 t; cvta.to.shared.u64 t, %1; cvt.u32.u64 %0, t; }"
        : "=r"(a) : "l"(p));
    return a;
}
__device__ __forceinline__ void ldmx4(uint32_t* r, uint32_t addr) {
    asm volatile("ldmatrix.sync.aligned.m8n8.x4.shared.b16 {%0,%1,%2,%3}, [%4];"
        : "=r"(r[0]), "=r"(r[1]), "=r"(r[2]), "=r"(r[3]) : "r"(addr));
}
__device__ __forceinline__ void mma_bf16(float* d, const uint32_t* a, const uint32_t* b) {
    asm volatile(
        "mma.sync.aligned.m16n8k16.row.col.f32.bf16.bf16.f32 "
        "{%0,%1,%2,%3}, {%4,%5,%6,%7}, {%8,%9}, {%0,%1,%2,%3};"
        : "+f"(d[0]), "+f"(d[1]), "+f"(d[2]), "+f"(d[3])
        : "r"(a[0]), "r"(a[1]), "r"(a[2]), "r"(a[3]), "r"(b[0]), "r"(b[1]));
}
__device__ __forceinline__ uint32_t cvt_bf16x2(float lo, float hi) {
    uint32_t r;
    asm("cvt.rn.bf16x2.f32 %0, %1, %2;" : "=r"(r) : "f"(hi), "f"(lo));
    return r;
}
#define SMEM_SWIZZLE_128B(byte_offset) \
    ((byte_offset) ^ (((byte_offset) >> 3) & 0x70))

// ===========================================================================
// bf16-split GEMM NT: C[M,N] = A[M,K] * B[N,K]^T   (fp32 I/O)
//   hi = truncate-to-bf16(x), lo = rn-bf16(x - hi); C = Ah*Bh + Ah*Bl + Al*Bh
// CTA tile 128x128, 8 warps (2m x 4n), warp tile 64x32, BK=64.
// Smem: per stage {Ah, Al, Bh, Bl}, each 128x64 bf16 (128B rows, SW128
// swizzle => conflict-free ldmatrix). 2 stages = 128KB.
// ===========================================================================
#define BM 128
#define BN 128
#define BK 64
#define NCHUNK (DIM / BK)        // 16
#define TILE_B (128 * 128)       // 16384 bytes (128 rows x 128B)
#define STAGE_B (4 * TILE_B)     // 64KB
#define GSMEM_TOTAL (2 * STAGE_B)

// convert one float4 (4 consecutive k) into packed hi-pair/lo-pair uint2s
__device__ __forceinline__ void split4(float4 v, uint2& hi, uint2& lo) {
    uint32_t bx = __float_as_uint(v.x), by = __float_as_uint(v.y);
    uint32_t bz = __float_as_uint(v.z), bw = __float_as_uint(v.w);
    hi.x = __byte_perm(bx, by, 0x7632);       // [bf16(x)_trunc, bf16(y)_trunc]
    hi.y = __byte_perm(bz, bw, 0x7632);
    float hx = __uint_as_float(bx & 0xFFFF0000u);
    float hy = __uint_as_float(by & 0xFFFF0000u);
    float hz = __uint_as_float(bz & 0xFFFF0000u);
    float hw = __uint_as_float(bw & 0xFFFF0000u);
    lo.x = cvt_bf16x2(v.x - hx, v.y - hy);
    lo.y = cvt_bf16x2(v.z - hz, v.w - hw);
}

__global__ __launch_bounds__(256) void gemm_mma(const float* __restrict__ A,
                                                const float* __restrict__ B,
                                                float* __restrict__ C,
                                                int M, int N, int K)
{
    extern __shared__ __align__(1024) char smem[];
    const uint32_t sb = smem_to_u32(smem);
    const int tid  = threadIdx.x;
    const int wid  = tid >> 5;
    const int lane = tid & 31;
    const int m0   = blockIdx.y * BM;
    const int n0   = blockIdx.x * BN;
    const int wm   = wid & 1;          // 0..1
    const int wn   = wid >> 1;         // 0..3

    // per-thread load/store mapping for fp32->bf16 staging (8 float4 per tile)
    // f = tid + it*256 ; row = f>>4 (0..127), colgrp = (f&15)*4 (bf16 elems)
    // ldmatrix lane geometry (constant per lane):
    const int aRow = wm * 64 + (lane & 7) + ((lane >> 3) & 1) * 8;
    const int aKb  = ((lane >> 4) & 1) * 16;          // byte offset in k
    const uint32_t aXor = (uint32_t)((aRow & 7) << 4);
    const int bRow = wn * 32 + (lane & 7) + ((lane >> 4) & 1) * 8;
    const int bKb  = ((lane >> 3) & 1) * 16;
    const uint32_t bXor = (uint32_t)((bRow & 7) << 4);

    float acc[4][4][4];
#pragma unroll
    for (int mt = 0; mt < 4; mt++)
#pragma unroll
        for (int nt = 0; nt < 4; nt++)
#pragma unroll
            for (int q = 0; q < 4; q++) acc[mt][nt][q] = 0.f;

    // ---- preload chunk 0 into stage 0 ----
    {
        char* st = smem;
#pragma unroll
        for (int it = 0; it < 8; it++) {
            int f = tid + (it << 8);
            int row = f >> 4;
            int cg  = (f & 15) << 2;
            uint32_t off = SMEM_SWIZZLE_128B((uint32_t)(row * 128 + cg * 2));
            float4 va = *(const float4*)(A + (size_t)(m0 + row) * K + cg);
            float4 vb = *(const float4*)(B + (size_t)(n0 + row) * K + cg);
            uint2 h, l;
            split4(va, h, l);
            *(uint2*)(st + off)              = h;
            *(uint2*)(st + TILE_B + off)     = l;
            split4(vb, h, l);
            *(uint2*)(st + 2 * TILE_B + off) = h;
            *(uint2*)(st + 3 * TILE_B + off) = l;
        }
    }
    __syncthreads();

    for (int c = 0; c < NCHUNK; c++) {
        const int buf = c & 1;
        const uint32_t sAh = sb + buf * STAGE_B;
        const uint32_t sAl = sAh + TILE_B;
        const uint32_t sBh = sAh + 2 * TILE_B;
        const uint32_t sBl = sAh + 3 * TILE_B;

        // prefetch next chunk's fp32 into registers (latency overlaps mma)
        float4 ra[8], rb[8];
        if (c + 1 < NCHUNK) {
            const float* Ap = A + (size_t)m0 * K + (c + 1) * BK;
            const float* Bp = B + (size_t)n0 * K + (c + 1) * BK;
#pragma unroll
            for (int it = 0; it < 8; it++) {
                int f = tid + (it << 8);
                int row = f >> 4;
                int cg  = (f & 15) << 2;
                ra[it] = *(const float4*)(Ap + (size_t)row * K + cg);
                rb[it] = *(const float4*)(Bp + (size_t)row * K + cg);
            }
        }

        // ---- mma over current chunk (4 k-steps of 16) ----
#pragma unroll
        for (int ks = 0; ks < 4; ks++) {
            uint32_t ah[4][4], al[4][4], bh[4][2], bl[4][2];
#pragma unroll
            for (int mt = 0; mt < 4; mt++) {
                uint32_t off = (uint32_t)((aRow + mt * 16) * 128) +
                               (((uint32_t)(ks * 32 + aKb)) ^ aXor);
                ldmx4(ah[mt], sAh + off);
                ldmx4(al[mt], sAl + off);
            }
#pragma unroll
            for (int np = 0; np < 2; np++) {
                uint32_t off = (uint32_t)((bRow + np * 16) * 128) +
                               (((uint32_t)(ks * 32 + bKb)) ^ bXor);
                uint32_t r[4];
                ldmx4(r, sBh + off);
                bh[2*np][0] = r[0]; bh[2*np][1] = r[1];
                bh[2*np+1][0] = r[2]; bh[2*np+1][1] = r[3];
                ldmx4(r, sBl + off);
                bl[2*np][0] = r[0]; bl[2*np][1] = r[1];
                bl[2*np+1][0] = r[2]; bl[2*np+1][1] = r[3];
            }
#pragma unroll
            for (int mt = 0; mt < 4; mt++)
#pragma unroll
                for (int nt = 0; nt < 4; nt++) {
                    mma_bf16(acc[mt][nt], ah[mt], bh[nt]);
                    mma_bf16(acc[mt][nt], ah[mt], bl[nt]);
                    mma_bf16(acc[mt][nt], al[mt], bh[nt]);
                }
        }

        // ---- convert prefetched regs into the other stage ----
        if (c + 1 < NCHUNK) {
            char* st = smem + (buf ^ 1) * STAGE_B;
#pragma unroll
            for (int it = 0; it < 8; it++) {
                int f = tid + (it << 8);
                int row = f >> 4;
                int cg  = (f & 15) << 2;
                uint32_t off = SMEM_SWIZZLE_128B((uint32_t)(row * 128 + cg * 2));
                uint2 h, l;
                split4(ra[it], h, l);
                *(uint2*)(st + off)              = h;
                *(uint2*)(st + TILE_B + off)     = l;
                split4(rb[it], h, l);
                *(uint2*)(st + 2 * TILE_B + off) = h;
                *(uint2*)(st + 3 * TILE_B + off) = l;
            }
        }
        __syncthreads();
    }

    // ---- epilogue ----
#pragma unroll
    for (int mt = 0; mt < 4; mt++) {
        int r0 = m0 + wm * 64 + mt * 16 + (lane >> 2);
#pragma unroll
        for (int nt = 0; nt < 4; nt++) {
            int c0 = n0 + wn * 32 + nt * 8 + (lane & 3) * 2;
            *(float2*)(C + (size_t)r0 * N + c0) =
                make_float2(acc[mt][nt][0], acc[mt][nt][1]);
            *(float2*)(C + (size_t)(r0 + 8) * N + c0) =
                make_float2(acc[mt][nt][2], acc[mt][nt][3]);
        }
    }
}

// ---------------------------------------------------------------------------
// RoPE (interleaved pairs) applied in-place to g_Q and g_K.
// ---------------------------------------------------------------------------
__global__ __launch_bounds__(256) void rope_kernel()
{
    int idx = blockIdx.x * blockDim.x + threadIdx.x;
    if (idx >= S_LEN * (DIM / 2)) return;
    int s = idx >> 9;
    int p = idx & 511;
    int i = p & 31;

    float e   = (float)(-(double)(2 * i) * 13.287712379549449 / 64.0);
    float inv = exp2f(e);
    float ang = (float)s * inv;
    float sn, cs;
    sincosf(ang, &sn, &cs);

    size_t off = (size_t)s * DIM + 2 * p;
    float q1 = g_Q[off], q2 = g_Q[off + 1];
    g_Q[off]     = q1 * cs - q2 * sn;
    g_Q[off + 1] = q1 * sn + q2 * cs;
    float k1 = g_K[off], k2 = g_K[off + 1];
    g_K[off]     = k1 * cs - k2 * sn;
    g_K[off + 1] = k1 * sn + k2 * cs;
}

// ---------------------------------------------------------------------------
// Sliding-window attention (flash-style, online softmax, fp32).
// ---------------------------------------------------------------------------
__global__ __launch_bounds__(256) void swa_kernel()
{
    __shared__ float Qs[64][64];
    __shared__ float KP[64][64];
    __shared__ float Vs[64][64];

    const int h  = blockIdx.y;
    const int q0 = blockIdx.x << 6;
    const int tid = threadIdx.x;
    const int tx  = tid & 15;
    const int ty  = tid >> 4;

    {
        const int qr  = tid >> 2;
        const int seg = (tid & 3) << 4;
        const float* src = g_Q + (size_t)(q0 + qr) * DIM + h * HD + seg;
#pragma unroll
        for (int j = 0; j < 16; j += 4) {
            float4 v = *(const float4*)(src + j);
            Qs[seg + j + 0][qr] = v.x; Qs[seg + j + 1][qr] = v.y;
            Qs[seg + j + 2][qr] = v.z; Qs[seg + j + 3][qr] = v.w;
        }
    }

    float m[4], l[4], acc[4][4];
#pragma unroll
    for (int r = 0; r < 4; r++) {
        m[r] = -1e30f; l[r] = 0.f;
#pragma unroll
        for (int c = 0; c < 4; c++) acc[r][c] = 0.f;
    }

    const int kt_begin = (q0 >= WIN) ? ((q0 - (WIN - 1)) >> 6) : 0;
    const int kt_end   = q0 >> 6;
    const float sc = 0.125f * 1.4426950408889634f;

    for (int kt = kt_begin; kt <= kt_end; kt++) {
        const int k0 = kt << 6;
        __syncthreads();

        {
            const int kr  = tid >> 2;
            const int seg = (tid & 3) << 4;
            const float* srcK = g_K + (size_t)(k0 + kr) * DIM + h * HD + seg;
#pragma unroll
            for (int j = 0; j < 16; j += 4) {
                float4 v = *(const float4*)(srcK + j);
                KP[seg + j + 0][kr] = v.x; KP[seg + j + 1][kr] = v.y;
                KP[seg + j + 2][kr] = v.z; KP[seg + j + 3][kr] = v.w;
            }
#pragma unroll
            for (int t = 0; t < 4; t++) {
                int f   = tid + (t << 8);
                int kr2 = f >> 4;
                int dc  = (f & 15) << 2;
                *(float4*)&Vs[kr2][dc] =
                    *(const float4*)(g_V + (size_t)(k0 + kr2) * DIM + h * HD + dc);
            }
        }
        __syncthreads();

        float s[4][4];
#pragma unroll
        for (int r = 0; r < 4; r++)
#pragma unroll
            for (int c = 0; c < 4; c++) s[r][c] = 0.f;
#pragma unroll
        for (int kk = 0; kk < 64; kk++) {
            float4 a = *(const float4*)&Qs[kk][ty << 2];
            float4 b = *(const float4*)&KP[kk][tx << 2];
            float avv[4] = {a.x, a.y, a.z, a.w};
            float bvv[4] = {b.x, b.y, b.z, b.w};
#pragma unroll
            for (int r = 0; r < 4; r++)
#pragma unroll
                for (int c = 0; c < 4; c++)
                    s[r][c] = fmaf(avv[r], bvv[c], s[r][c]);
        }

#pragma unroll
        for (int r = 0; r < 4; r++) {
            int qg = q0 + (ty << 2) + r;
#pragma unroll
            for (int c = 0; c < 4; c++) {
                int kg = k0 + (tx << 2) + c;
                bool ok = (kg <= qg) && (kg + WIN > qg);
                s[r][c] = ok ? s[r][c] * sc : -3.0e38f;
            }
        }

#pragma unroll
        for (int r = 0; r < 4; r++) {
            float mt = fmaxf(fmaxf(s[r][0], s[r][1]), fmaxf(s[r][2], s[r][3]));
#pragma unroll
            for (int o = 8; o > 0; o >>= 1)
                mt = fmaxf(mt, __shfl_xor_sync(0xffffffffu, mt, o));
            float mnew = fmaxf(m[r], mt);
            float corr = exp2f(m[r] - mnew);
            float sum  = 0.f;
#pragma unroll
            for (int c = 0; c < 4; c++) {
                float p = exp2f(s[r][c] - mnew);
                s[r][c] = p;
                sum += p;
            }
#pragma unroll
            for (int o = 8; o > 0; o >>= 1)
                sum += __shfl_xor_sync(0xffffffffu, sum, o);
            l[r] = l[r] * corr + sum;
            m[r] = mnew;
#pragma unroll
            for (int c = 0; c < 4; c++) acc[r][c] *= corr;
        }

        __syncthreads();
#pragma unroll
        for (int r = 0; r < 4; r++)
#pragma unroll
            for (int c = 0; c < 4; c++)
                KP[(ty << 2) + r][(tx << 2) + c] = s[r][c];
        __syncthreads();

#pragma unroll
        for (int kk = 0; kk < 64; kk++) {
            float4 vv = *(const float4*)&Vs[kk][tx << 2];
            float vvv[4] = {vv.x, vv.y, vv.z, vv.w};
#pragma unroll
            for (int r = 0; r < 4; r++) {
                float p = KP[(ty << 2) + r][kk];
#pragma unroll
                for (int c = 0; c < 4; c++)
                    acc[r][c] = fmaf(p, vvv[c], acc[r][c]);
            }
        }
    }

#pragma unroll
    for (int r = 0; r < 4; r++) {
        float inv = 1.f / l[r];
        float4 o = make_float4(acc[r][0] * inv, acc[r][1] * inv,
                               acc[r][2] * inv, acc[r][3] * inv);
        *(float4*)(g_O + (size_t)(q0 + (ty << 2) + r) * DIM + h * HD + (tx << 2)) = o;
    }
}

// ---------------------------------------------------------------------------
extern "C" void kernel_launch(void* const* d_in, const int* in_sizes, int n_in,
                              void* d_out, int out_size)
{
    const float* x  = (const float*)d_in[0];
    const float* Wq = (const float*)d_in[1];
    const float* Wk = (const float*)d_in[2];
    const float* Wv = (const float*)d_in[3];
    const float* Wo = (const float*)d_in[4];
    float* out = (float*)d_out;
    (void)in_sizes; (void)n_in; (void)out_size;

    static float *pQ = nullptr, *pK = nullptr, *pV = nullptr, *pO = nullptr;
    if (!pQ) {
        cudaGetSymbolAddress((void**)&pQ, g_Q);
        cudaGetSymbolAddress((void**)&pK, g_K);
        cudaGetSymbolAddress((void**)&pV, g_V);
        cudaGetSymbolAddress((void**)&pO, g_O);
        cudaFuncSetAttribute(gemm_mma, cudaFuncAttributeMaxDynamicSharedMemorySize,
                             GSMEM_TOTAL);
    }

    dim3 gg(DIM / BN, S_LEN / BM);   // (8, 64)
    gemm_mma<<<gg, 256, GSMEM_TOTAL>>>(x, Wq, pQ, S_LEN, DIM, DIM);
    gemm_mma<<<gg, 256, GSMEM_TOTAL>>>(x, Wk, pK, S_LEN, DIM, DIM);
    gemm_mma<<<gg, 256, GSMEM_TOTAL>>>(x, Wv, pV, S_LEN, DIM, DIM);

    rope_kernel<<<(S_LEN * (DIM / 2)) / 256, 256>>>();

    swa_kernel<<<dim3(S_LEN / 64, NH), 256>>>();

    gemm_mma<<<gg, 256, GSMEM_TOTAL>>>(pO, Wo, out, S_LEN, DIM, DIM);
}

// round 5
// speedup vs baseline: 2.6622x; 1.3599x over previous
#include <cuda_runtime.h>
#include <cuda_bf16.h>
#include <cstdint>

#define S_LEN 8192
#define DIM   1024
#define NH    16
#define HD    64
#define WIN   512

// Scratch (device globals: allocation-guard safe). 4 x 32MB.
__device__ float g_Q[S_LEN * DIM];
__device__ float g_K[S_LEN * DIM];
__device__ float g_V[S_LEN * DIM];
__device__ float g_O[S_LEN * DIM];

// ===========================================================================
// mma.sync helpers (sm_80+ path: tcgen05 is gated off at PTX target sm_100)
// ===========================================================================
__device__ __forceinline__ uint32_t smem_to_u32(const void* p) {
    uint32_t a;
    asm("{ .reg .u64 t; cvta.to.shared.u64 t, %1; cvt.u32.u64 %0, t; }"
        : "=r"(a) : "l"(p));
    return a;
}
__device__ __forceinline__ void ldmx4(uint32_t* r, uint32_t addr) {
    asm volatile("ldmatrix.sync.aligned.m8n8.x4.shared.b16 {%0,%1,%2,%3}, [%4];"
        : "=r"(r[0]), "=r"(r[1]), "=r"(r[2]), "=r"(r[3]) : "r"(addr));
}
__device__ __forceinline__ void ldmx4t(uint32_t* r, uint32_t addr) {
    asm volatile("ldmatrix.sync.aligned.m8n8.x4.trans.shared.b16 {%0,%1,%2,%3}, [%4];"
        : "=r"(r[0]), "=r"(r[1]), "=r"(r[2]), "=r"(r[3]) : "r"(addr));
}
__device__ __forceinline__ void mma_bf16(float* d, const uint32_t* a, const uint32_t* b) {
    asm volatile(
        "mma.sync.aligned.m16n8k16.row.col.f32.bf16.bf16.f32 "
        "{%0,%1,%2,%3}, {%4,%5,%6,%7}, {%8,%9}, {%0,%1,%2,%3};"
        : "+f"(d[0]), "+f"(d[1]), "+f"(d[2]), "+f"(d[3])
        : "r"(a[0]), "r"(a[1]), "r"(a[2]), "r"(a[3]), "r"(b[0]), "r"(b[1]));
}
__device__ __forceinline__ uint32_t cvt_bf16x2(float lo, float hi) {
    uint32_t r;
    asm("cvt.rn.bf16x2.f32 %0, %1, %2;" : "=r"(r) : "f"(hi), "f"(lo));
    return r;
}
#define SMEM_SWIZZLE_128B(byte_offset) \
    ((byte_offset) ^ (((byte_offset) >> 3) & 0x70))

// convert one float4 (4 consecutive k) into packed hi-pair/lo-pair uint2s
__device__ __forceinline__ void split4(float4 v, uint2& hi, uint2& lo) {
    uint32_t bx = __float_as_uint(v.x), by = __float_as_uint(v.y);
    uint32_t bz = __float_as_uint(v.z), bw = __float_as_uint(v.w);
    hi.x = __byte_perm(bx, by, 0x7632);
    hi.y = __byte_perm(bz, bw, 0x7632);
    float hx = __uint_as_float(bx & 0xFFFF0000u);
    float hy = __uint_as_float(by & 0xFFFF0000u);
    float hz = __uint_as_float(bz & 0xFFFF0000u);
    float hw = __uint_as_float(bw & 0xFFFF0000u);
    lo.x = cvt_bf16x2(v.x - hx, v.y - hy);
    lo.y = cvt_bf16x2(v.z - hz, v.w - hw);
}
__device__ __forceinline__ void pack_split2(float e0, float e1,
                                            uint32_t& hi, uint32_t& lo) {
    uint32_t b0 = __float_as_uint(e0), b1 = __float_as_uint(e1);
    hi = __byte_perm(b0, b1, 0x7632);
    float h0 = __uint_as_float(b0 & 0xFFFF0000u);
    float h1 = __uint_as_float(b1 & 0xFFFF0000u);
    lo = cvt_bf16x2(e0 - h0, e1 - h1);
}
// fast exp2 on the FMA pipe (no MUFU). Max rel err ~2.4e-6 on f in [-.5,.5].
__device__ __forceinline__ float exp2f_fast(float x) {
    x = fmaxf(x, -126.0f);
    float n = rintf(x);
    float f = x - n;
    float p = 0.00133335581f;
    p = fmaf(p, f, 0.00961812911f);
    p = fmaf(p, f, 0.05550410866f);
    p = fmaf(p, f, 0.24022650700f);
    p = fmaf(p, f, 0.69314718056f);
    p = fmaf(p, f, 1.0f);
    int e = (int)n;
    return p * __int_as_float((e + 127) << 23);
}

// ===========================================================================
// bf16-split GEMM NT (unchanged from R4): C[M,N] = A[M,K] * B[N,K]^T
// ===========================================================================
#define BM 128
#define BN 128
#define BK 64
#define NCHUNK (DIM / BK)
#define TILE_B (128 * 128)
#define STAGE_B (4 * TILE_B)
#define GSMEM_TOTAL (2 * STAGE_B)

__global__ __launch_bounds__(256) void gemm_mma(const float* __restrict__ A,
                                                const float* __restrict__ B,
                                                float* __restrict__ C,
                                                int M, int N, int K)
{
    extern __shared__ __align__(1024) char smem[];
    const uint32_t sb = smem_to_u32(smem);
    const int tid  = threadIdx.x;
    const int wid  = tid >> 5;
    const int lane = tid & 31;
    const int m0   = blockIdx.y * BM;
    const int n0   = blockIdx.x * BN;
    const int wm   = wid & 1;
    const int wn   = wid >> 1;

    const int aRow = wm * 64 + (lane & 15);
    const int aKb  = ((lane >> 4) & 1) * 16;
    const uint32_t aXor = (uint32_t)((aRow & 7) << 4);
    const int bRow = wn * 32 + (lane & 7) + ((lane >> 4) & 1) * 8;
    const int bKb  = ((lane >> 3) & 1) * 16;
    const uint32_t bXor = (uint32_t)((bRow & 7) << 4);

    float acc[4][4][4];
#pragma unroll
    for (int mt = 0; mt < 4; mt++)
#pragma unroll
        for (int nt = 0; nt < 4; nt++)
#pragma unroll
            for (int q = 0; q < 4; q++) acc[mt][nt][q] = 0.f;

    {
        char* st = smem;
#pragma unroll
        for (int it = 0; it < 8; it++) {
            int f = tid + (it << 8);
            int row = f >> 4;
            int cg  = (f & 15) << 2;
            uint32_t off = SMEM_SWIZZLE_128B((uint32_t)(row * 128 + cg * 2));
            float4 va = *(const float4*)(A + (size_t)(m0 + row) * K + cg);
            float4 vb = *(const float4*)(B + (size_t)(n0 + row) * K + cg);
            uint2 h, l;
            split4(va, h, l);
            *(uint2*)(st + off)              = h;
            *(uint2*)(st + TILE_B + off)     = l;
            split4(vb, h, l);
            *(uint2*)(st + 2 * TILE_B + off) = h;
            *(uint2*)(st + 3 * TILE_B + off) = l;
        }
    }
    __syncthreads();

    for (int c = 0; c < NCHUNK; c++) {
        const int buf = c & 1;
        const uint32_t sAh = sb + buf * STAGE_B;
        const uint32_t sAl = sAh + TILE_B;
        const uint32_t sBh = sAh + 2 * TILE_B;
        const uint32_t sBl = sAh + 3 * TILE_B;

        float4 ra[8], rb[8];
        if (c + 1 < NCHUNK) {
            const float* Ap = A + (size_t)m0 * K + (c + 1) * BK;
            const float* Bp = B + (size_t)n0 * K + (c + 1) * BK;
#pragma unroll
            for (int it = 0; it < 8; it++) {
                int f = tid + (it << 8);
                int row = f >> 4;
                int cg  = (f & 15) << 2;
                ra[it] = *(const float4*)(Ap + (size_t)row * K + cg);
                rb[it] = *(const float4*)(Bp + (size_t)row * K + cg);
            }
        }

#pragma unroll
        for (int ks = 0; ks < 4; ks++) {
            uint32_t ah[4][4], al[4][4], bh[4][2], bl[4][2];
#pragma unroll
            for (int mt = 0; mt < 4; mt++) {
                uint32_t off = (uint32_t)((aRow + mt * 16) * 128) +
                               (((uint32_t)(ks * 32 + aKb)) ^ aXor);
                ldmx4(ah[mt], sAh + off);
                ldmx4(al[mt], sAl + off);
            }
#pragma unroll
            for (int np = 0; np < 2; np++) {
                uint32_t off = (uint32_t)((bRow + np * 16) * 128) +
                               (((uint32_t)(ks * 32 + bKb)) ^ bXor);
                uint32_t r[4];
                ldmx4(r, sBh + off);
                bh[2*np][0] = r[0]; bh[2*np][1] = r[1];
                bh[2*np+1][0] = r[2]; bh[2*np+1][1] = r[3];
                ldmx4(r, sBl + off);
                bl[2*np][0] = r[0]; bl[2*np][1] = r[1];
                bl[2*np+1][0] = r[2]; bl[2*np+1][1] = r[3];
            }
#pragma unroll
            for (int mt = 0; mt < 4; mt++)
#pragma unroll
                for (int nt = 0; nt < 4; nt++) {
                    mma_bf16(acc[mt][nt], ah[mt], bh[nt]);
                    mma_bf16(acc[mt][nt], ah[mt], bl[nt]);
                    mma_bf16(acc[mt][nt], al[mt], bh[nt]);
                }
        }

        if (c + 1 < NCHUNK) {
            char* st = smem + (buf ^ 1) * STAGE_B;
#pragma unroll
            for (int it = 0; it < 8; it++) {
                int f = tid + (it << 8);
                int row = f >> 4;
                int cg  = (f & 15) << 2;
                uint32_t off = SMEM_SWIZZLE_128B((uint32_t)(row * 128 + cg * 2));
                uint2 h, l;
                split4(ra[it], h, l);
                *(uint2*)(st + off)              = h;
                *(uint2*)(st + TILE_B + off)     = l;
                split4(rb[it], h, l);
                *(uint2*)(st + 2 * TILE_B + off) = h;
                *(uint2*)(st + 3 * TILE_B + off) = l;
            }
        }
        __syncthreads();
    }

#pragma unroll
    for (int mt = 0; mt < 4; mt++) {
        int r0 = m0 + wm * 64 + mt * 16 + (lane >> 2);
#pragma unroll
        for (int nt = 0; nt < 4; nt++) {
            int c0 = n0 + wn * 32 + nt * 8 + (lane & 3) * 2;
            *(float2*)(C + (size_t)r0 * N + c0) =
                make_float2(acc[mt][nt][0], acc[mt][nt][1]);
            *(float2*)(C + (size_t)(r0 + 8) * N + c0) =
                make_float2(acc[mt][nt][2], acc[mt][nt][3]);
        }
    }
}

// ---------------------------------------------------------------------------
// RoPE (interleaved pairs) applied in-place to g_Q and g_K.
// ---------------------------------------------------------------------------
__global__ __launch_bounds__(256) void rope_kernel()
{
    int idx = blockIdx.x * blockDim.x + threadIdx.x;
    if (idx >= S_LEN * (DIM / 2)) return;
    int s = idx >> 9;
    int p = idx & 511;
    int i = p & 31;

    float e   = (float)(-(double)(2 * i) * 13.287712379549449 / 64.0);
    float inv = exp2f(e);
    float ang = (float)s * inv;
    float sn, cs;
    sincosf(ang, &sn, &cs);

    size_t off = (size_t)s * DIM + 2 * p;
    float q1 = g_Q[off], q2 = g_Q[off + 1];
    g_Q[off]     = q1 * cs - q2 * sn;
    g_Q[off + 1] = q1 * sn + q2 * cs;
    float k1 = g_K[off], k2 = g_K[off + 1];
    g_K[off]     = k1 * cs - k2 * sn;
    g_K[off + 1] = k1 * sn + k2 * cs;
}

// ===========================================================================
// Sliding-window attention with mma.sync + polynomial exp2.
// CTA = (128 queries, 1 head), 8 warps (16 q-rows each). K-tiles of 64 keys.
// Q/K split hi/lo (3-product QK), P/V split hi/lo (3-product PV).
// Smem (64KB): Qh,Ql (16K ea), Kh,Kl (8K ea), Vh,Vl (8K ea), all 128B rows
// SW128-swizzled. V stored natural [k][d]; PV B-frags via ldmatrix.x4.trans.
// ===========================================================================
#define ASMEM_TOTAL 65536
#define OFF_QH 0
#define OFF_QL 16384
#define OFF_KH 32768
#define OFF_KL 40960
#define OFF_VH 49152
#define OFF_VL 57344

__global__ __launch_bounds__(256) void swa_mma()
{
    extern __shared__ __align__(1024) char smem[];
    const uint32_t sb = smem_to_u32(smem);
    const int h   = blockIdx.y;
    const int q0  = blockIdx.x * 128;
    const int tid = threadIdx.x;
    const int w   = tid >> 5;
    const int lane = tid & 31;

    // ---- stage Q tile: 128 rows x 64 f32 -> Qh/Ql ----
#pragma unroll
    for (int it = 0; it < 8; it++) {
        int f = tid + (it << 8);
        int row = f >> 4;
        int cg  = (f & 15) << 2;
        float4 v = *(const float4*)(g_Q + (size_t)(q0 + row) * DIM + h * HD + cg);
        uint2 hi, lo;
        split4(v, hi, lo);
        uint32_t off = SMEM_SWIZZLE_128B((uint32_t)(row * 128 + cg * 2));
        *(uint2*)(smem + OFF_QH + off) = hi;
        *(uint2*)(smem + OFF_QL + off) = lo;
    }
    __syncthreads();

    // ---- preload Q fragments (registers, reused across all k-tiles) ----
    uint32_t qh[4][4], ql[4][4];
    {
        const int aRow = w * 16 + (lane & 15);
        const uint32_t aSw = (uint32_t)((aRow & 7) << 4);
#pragma unroll
        for (int ks = 0; ks < 4; ks++) {
            uint32_t off = (uint32_t)(aRow * 128) +
                           (((uint32_t)(ks * 32 + ((lane >> 4) & 1) * 16)) ^ aSw);
            ldmx4(qh[ks], sb + OFF_QH + off);
            ldmx4(ql[ks], sb + OFF_QL + off);
        }
    }

    // lane geometry for K (B-frag) and V (trans B-frag)
    const int bRow = (lane & 7) + ((lane >> 4) & 1) * 8;
    const int bKb  = ((lane >> 3) & 1) * 16;
    const uint32_t bSw = (uint32_t)((bRow & 7) << 4);
    const int vRow = (lane & 7) + ((lane >> 3) & 1) * 8;
    const int vCb  = ((lane >> 4) & 1) * 16;
    const uint32_t vSw = (uint32_t)((vRow & 7) << 4);

    float m0 = -1e30f, m1 = -1e30f, l0 = 0.f, l1 = 0.f;
    float oacc[8][4];
#pragma unroll
    for (int j = 0; j < 8; j++)
#pragma unroll
        for (int q = 0; q < 4; q++) oacc[j][q] = 0.f;

    const int kt_begin = (q0 >= WIN) ? ((q0 - WIN + 1) >> 6) : 0;
    const int kt_end   = (q0 + 127) >> 6;
    const float sc = 0.125f * 1.4426950408889634f;   // 1/sqrt(64)*log2(e)

    // ---- stage first K/V tile ----
    {
        const int k0 = kt_begin << 6;
#pragma unroll
        for (int it = 0; it < 4; it++) {
            int f = tid + (it << 8);
            int row = f >> 4;
            int cg  = (f & 15) << 2;
            uint32_t off = SMEM_SWIZZLE_128B((uint32_t)(row * 128 + cg * 2));
            uint2 hi, lo;
            float4 vk = *(const float4*)(g_K + (size_t)(k0 + row) * DIM + h * HD + cg);
            split4(vk, hi, lo);
            *(uint2*)(smem + OFF_KH + off) = hi;
            *(uint2*)(smem + OFF_KL + off) = lo;
            float4 vv = *(const float4*)(g_V + (size_t)(k0 + row) * DIM + h * HD + cg);
            split4(vv, hi, lo);
            *(uint2*)(smem + OFF_VH + off) = hi;
            *(uint2*)(smem + OFF_VL + off) = lo;
        }
    }
    __syncthreads();

    const int qg0 = q0 + w * 16 + (lane >> 2);
    const int qg1 = qg0 + 8;

    for (int kt = kt_begin; kt <= kt_end; kt++) {
        const int k0 = kt << 6;

        // prefetch next tile's fp32 into registers
        float4 rk[4], rv[4];
        if (kt < kt_end) {
            const int kn = (kt + 1) << 6;
#pragma unroll
            for (int it = 0; it < 4; it++) {
                int f = tid + (it << 8);
                int row = f >> 4;
                int cg  = (f & 15) << 2;
                rk[it] = *(const float4*)(g_K + (size_t)(kn + row) * DIM + h * HD + cg);
                rv[it] = *(const float4*)(g_V + (size_t)(kn + row) * DIM + h * HD + cg);
            }
        }

        // ---- scores S = Q K^T (3-product split) ----
        float sacc[8][4];
#pragma unroll
        for (int j = 0; j < 8; j++)
#pragma unroll
            for (int q = 0; q < 4; q++) sacc[j][q] = 0.f;

#pragma unroll
        for (int ks = 0; ks < 4; ks++) {
#pragma unroll
            for (int np = 0; np < 4; np++) {
                uint32_t off = (uint32_t)((np * 16 + bRow) * 128) +
                               (((uint32_t)(ks * 32 + bKb)) ^ bSw);
                uint32_t kh4[4], kl4[4];
                ldmx4(kh4, sb + OFF_KH + off);
                ldmx4(kl4, sb + OFF_KL + off);
                mma_bf16(sacc[2*np],   qh[ks], kh4);
                mma_bf16(sacc[2*np],   qh[ks], kl4);
                mma_bf16(sacc[2*np],   ql[ks], kh4);
                mma_bf16(sacc[2*np+1], qh[ks], kh4 + 2);
                mma_bf16(sacc[2*np+1], qh[ks], kl4 + 2);
                mma_bf16(sacc[2*np+1], ql[ks], kh4 + 2);
            }
        }

        // ---- mask + scale ----
#pragma unroll
        for (int j = 0; j < 8; j++) {
            int kg = k0 + 8 * j + ((lane & 3) << 1);
            sacc[j][0] = (kg   <= qg0 && kg   + WIN > qg0) ? sacc[j][0] * sc : -1e30f;
            sacc[j][1] = (kg+1 <= qg0 && kg+1 + WIN > qg0) ? sacc[j][1] * sc : -1e30f;
            sacc[j][2] = (kg   <= qg1 && kg   + WIN > qg1) ? sacc[j][2] * sc : -1e30f;
            sacc[j][3] = (kg+1 <= qg1 && kg+1 + WIN > qg1) ? sacc[j][3] * sc : -1e30f;
        }

        // ---- online softmax (row stats over 4 lanes) ----
        float t0 = -1e30f, t1 = -1e30f;
#pragma unroll
        for (int j = 0; j < 8; j++) {
            t0 = fmaxf(t0, fmaxf(sacc[j][0], sacc[j][1]));
            t1 = fmaxf(t1, fmaxf(sacc[j][2], sacc[j][3]));
        }
        t0 = fmaxf(t0, __shfl_xor_sync(0xffffffffu, t0, 1));
        t0 = fmaxf(t0, __shfl_xor_sync(0xffffffffu, t0, 2));
        t1 = fmaxf(t1, __shfl_xor_sync(0xffffffffu, t1, 1));
        t1 = fmaxf(t1, __shfl_xor_sync(0xffffffffu, t1, 2));
        float mn0 = fmaxf(m0, t0), mn1 = fmaxf(m1, t1);
        float c0 = exp2f_fast(m0 - mn0), c1 = exp2f_fast(m1 - mn1);
        m0 = mn0; m1 = mn1;

        float s0 = 0.f, s1 = 0.f;
#pragma unroll
        for (int j = 0; j < 8; j++) {
            float p0 = exp2f_fast(sacc[j][0] - m0);
            float p1 = exp2f_fast(sacc[j][1] - m0);
            float p2 = exp2f_fast(sacc[j][2] - m1);
            float p3 = exp2f_fast(sacc[j][3] - m1);
            sacc[j][0] = p0; sacc[j][1] = p1; sacc[j][2] = p2; sacc[j][3] = p3;
            s0 += p0 + p1; s1 += p2 + p3;
        }
        s0 += __shfl_xor_sync(0xffffffffu, s0, 1);
        s0 += __shfl_xor_sync(0xffffffffu, s0, 2);
        s1 += __shfl_xor_sync(0xffffffffu, s1, 1);
        s1 += __shfl_xor_sync(0xffffffffu, s1, 2);
        l0 = l0 * c0 + s0;
        l1 = l1 * c1 + s1;
#pragma unroll
        for (int j = 0; j < 8; j++) {
            oacc[j][0] *= c0; oacc[j][1] *= c0;
            oacc[j][2] *= c1; oacc[j][3] *= c1;
        }

        // ---- pack P into A-fragments (hi/lo split), registers only ----
        uint32_t aPh[4][4], aPl[4][4];
#pragma unroll
        for (int t = 0; t < 4; t++) {
            pack_split2(sacc[2*t][0],   sacc[2*t][1],   aPh[t][0], aPl[t][0]);
            pack_split2(sacc[2*t][2],   sacc[2*t][3],   aPh[t][1], aPl[t][1]);
            pack_split2(sacc[2*t+1][0], sacc[2*t+1][1], aPh[t][2], aPl[t][2]);
            pack_split2(sacc[2*t+1][2], sacc[2*t+1][3], aPh[t][3], aPl[t][3]);
        }

        // ---- O += P V (3-product split), V via ldmatrix.trans ----
#pragma unroll
        for (int t = 0; t < 4; t++) {
#pragma unroll
            for (int j2 = 0; j2 < 4; j2++) {
                uint32_t off = (uint32_t)((t * 16 + vRow) * 128) +
                               (((uint32_t)(j2 * 32 + vCb)) ^ vSw);
                uint32_t vh4[4], vl4[4];
                ldmx4t(vh4, sb + OFF_VH + off);
                ldmx4t(vl4, sb + OFF_VL + off);
                mma_bf16(oacc[2*j2],   aPh[t], vh4);
                mma_bf16(oacc[2*j2],   aPh[t], vl4);
                mma_bf16(oacc[2*j2],   aPl[t], vh4);
                mma_bf16(oacc[2*j2+1], aPh[t], vh4 + 2);
                mma_bf16(oacc[2*j2+1], aPh[t], vl4 + 2);
                mma_bf16(oacc[2*j2+1], aPl[t], vh4 + 2);
            }
        }

        // ---- commit prefetched tile into smem ----
        __syncthreads();
        if (kt < kt_end) {
#pragma unroll
            for (int it = 0; it < 4; it++) {
                int f = tid + (it << 8);
                int row = f >> 4;
                int cg  = (f & 15) << 2;
                uint32_t off = SMEM_SWIZZLE_128B((uint32_t)(row * 128 + cg * 2));
                uint2 hi, lo;
                split4(rk[it], hi, lo);
                *(uint2*)(smem + OFF_KH + off) = hi;
                *(uint2*)(smem + OFF_KL + off) = lo;
                split4(rv[it], hi, lo);
                *(uint2*)(smem + OFF_VH + off) = hi;
                *(uint2*)(smem + OFF_VL + off) = lo;
            }
            __syncthreads();
        }
    }

    // ---- epilogue: O /= l ----
    float inv0 = 1.f / l0, inv1 = 1.f / l1;
    const int r0g = q0 + w * 16 + (lane >> 2);
#pragma unroll
    for (int j = 0; j < 8; j++) {
        int c0 = h * HD + 8 * j + ((lane & 3) << 1);
        *(float2*)(g_O + (size_t)r0g * DIM + c0) =
            make_float2(oacc[j][0] * inv0, oacc[j][1] * inv0);
        *(float2*)(g_O + (size_t)(r0g + 8) * DIM + c0) =
            make_float2(oacc[j][2] * inv1, oacc[j][3] * inv1);
    }
}

// ---------------------------------------------------------------------------
extern "C" void kernel_launch(void* const* d_in, const int* in_sizes, int n_in,
                              void* d_out, int out_size)
{
    const float* x  = (const float*)d_in[0];
    const float* Wq = (const float*)d_in[1];
    const float* Wk = (const float*)d_in[2];
    const float* Wv = (const float*)d_in[3];
    const float* Wo = (const float*)d_in[4];
    float* out = (float*)d_out;
    (void)in_sizes; (void)n_in; (void)out_size;

    static float *pQ = nullptr, *pK = nullptr, *pV = nullptr, *pO = nullptr;
    if (!pQ) {
        cudaGetSymbolAddress((void**)&pQ, g_Q);
        cudaGetSymbolAddress((void**)&pK, g_K);
        cudaGetSymbolAddress((void**)&pV, g_V);
        cudaGetSymbolAddress((void**)&pO, g_O);
        cudaFuncSetAttribute(gemm_mma, cudaFuncAttributeMaxDynamicSharedMemorySize,
                             GSMEM_TOTAL);
        cudaFuncSetAttribute(swa_mma, cudaFuncAttributeMaxDynamicSharedMemorySize,
                             ASMEM_TOTAL);
    }

    dim3 gg(DIM / BN, S_LEN / BM);   // (8, 64)
    gemm_mma<<<gg, 256, GSMEM_TOTAL>>>(x, Wq, pQ, S_LEN, DIM, DIM);
    gemm_mma<<<gg, 256, GSMEM_TOTAL>>>(x, Wk, pK, S_LEN, DIM, DIM);
    gemm_mma<<<gg, 256, GSMEM_TOTAL>>>(x, Wv, pV, S_LEN, DIM, DIM);

    rope_kernel<<<(S_LEN * (DIM / 2)) / 256, 256>>>();

    swa_mma<<<dim3(S_LEN / 128, NH), 256, ASMEM_TOTAL>>>();

    gemm_mma<<<gg, 256, GSMEM_TOTAL>>>(pO, Wo, out, S_LEN, DIM, DIM);
}